// round 7
// baseline (speedup 1.0000x reference)
#include <cuda_runtime.h>
#include <cuda_bf16.h>

// Polyphase resample up=3, down=2, F=1023 taps (341 per phase).
// Per phase p (out[j], j = jp + 3k): y_p[k] = sum_q (3*h[p+3q]) * x[c_p + 2k - q]
//   jp = {1,0,2}[p],  c_p = {171,170,171}[p]
//
// f32x2 FMA: 16 outputs/thread as 8 packed accumulators pairing (k+r, k+r+8).
// Window refills: 2 conflict-free LDS.32 (word stride 33) + mov.b64 pack.
// Filter taps: LDS.128 broadcast prefetch, qp-parity alternating slots (0 MOVs).
// Outputs staged in smem, written as coalesced STG.128.

constexpr int NTAP3    = 341;
constexpr int HSTRIDE  = 342;    // padded per-phase tap stride (16B align)
constexpr int KTILE    = 1024;
constexpr int NTHREADS = 192;    // 6 warps: 2 per phase
constexpr int R        = 8;
constexpr int WIN      = 2 * KTILE + 340;        // 2388 x-samples
constexpr int XSN      = WIN + (WIN >> 5) + 8;   // skewed float window
constexpr int YPITCH   = 1091;

constexpr int XS_FLOATS = ((XSN + 3) & ~3);                // 16B-align next
constexpr int POOL_FLOATS_A = XS_FLOATS + 2 * 3 * HSTRIDE; // xs + hdup(float2)
constexpr int POOL_FLOATS_B = 3 * YPITCH + 8;              // y staging
constexpr int POOL_FLOATS = POOL_FLOATS_A > POOL_FLOATS_B ? POOL_FLOATS_A
                                                          : POOL_FLOATS_B;

typedef unsigned long long ull;

__device__ __forceinline__ int ss(int i) { return i + (i >> 5); }

__device__ __forceinline__ ull pk2(const float* __restrict__ xs, int e) {
    float lo = xs[ss(e)];
    float hi = xs[ss(e + 16)];
    ull r;
    asm("mov.b64 %0, {%1, %2};" : "=l"(r) : "f"(lo), "f"(hi));
    return r;
}

__device__ __forceinline__ void fma2(ull& d, ull a, ull b) {
    asm("fma.rn.f32x2 %0, %1, %2, %0;" : "+l"(d) : "l"(a), "l"(b));
}

__global__ void __launch_bounds__(NTHREADS, 4)
resample_poly_kernel(const float* __restrict__ x, const float* __restrict__ h,
                     float* __restrict__ out, int N, int ktotal, int nout)
{
    __shared__ __align__(16) float pool[POOL_FLOATS];
    float*  xs   = pool;
    float2* hdup = reinterpret_cast<float2*>(pool + XS_FLOATS);

    const int tid = threadIdx.x;
    const int K0  = blockIdx.x * KTILE;
    const int ws  = 2 * K0 - 170;

    for (int i = tid; i < WIN; i += NTHREADS) {
        int g = ws + i;
        xs[ss(i)] = (g >= 0 && g < N) ? x[g] : 0.0f;
    }
    for (int m = tid; m < 3 * NTAP3; m += NTHREADS) {
        int p = m % 3, q = m / 3;
        float v = 3.0f * h[m];
        hdup[p * HSTRIDE + q] = make_float2(v, v);
    }
    __syncthreads();

    const int wid  = tid >> 5;
    const int lane = tid & 31;
    const int p    = wid >> 1;                 // phase (2 warps each)
    const int tip  = ((wid & 1) << 5) | lane;  // 0..63 within phase
    const int cp   = (p == 1) ? 170 : 171;
    const int b    = cp + 170 + 32 * tip;

    ull acc[R], PA[R], PB[R];
    #pragma unroll
    for (int r = 0; r < R; ++r) acc[r] = 0ull;
    #pragma unroll
    for (int r = 0; r < R; ++r) PA[r] = pk2(xs, b + 2 * r);       // even q
    #pragma unroll
    for (int r = 0; r < R; ++r) PB[r] = pk2(xs, b - 1 + 2 * r);   // odd q

    const ull* hq = reinterpret_cast<const ull*>(hdup + p * HSTRIDE);

    // h slots: even qp consumes hr[0..1], odd qp consumes hr[2..3].
    ull hr[4];
    hr[0] = hq[0]; hr[1] = hq[1]; hr[2] = hq[2]; hr[3] = hq[3];

    for (int qo = 0; qo < 336; qo += 16) {
        #pragma unroll
        for (int qp = 0; qp < 8; ++qp) {
            const int q  = qo + 2 * qp;
            const int hs = (qp & 1) << 1;      // 0 or 2 (compile-time)
            #pragma unroll
            for (int r = 0; r < R; ++r) fma2(acc[r], PA[(r - qp) & 7], hr[hs]);
            PA[(7 - qp) & 7] = pk2(xs, b - q - 2);
            #pragma unroll
            for (int r = 0; r < R; ++r) fma2(acc[r], PB[(r - qp) & 7], hr[hs + 1]);
            PB[(7 - qp) & 7] = pk2(xs, b - q - 3);
            // Prefetch taps (q+4, q+5) into this parity's slots (used at qp+2).
            *reinterpret_cast<ulonglong2*>(&hr[hs]) =
                *reinterpret_cast<const ulonglong2*>(hq + q + 4);
        }
    }
    #pragma unroll
    for (int q = 336; q < 341; ++q) {
        ull hh = hq[q];
        #pragma unroll
        for (int r = 0; r < R; ++r) {
            ull pxx = pk2(xs, b - q + 2 * r);
            fma2(acc[r], pxx, hh);
        }
    }

    // ---- Epilogue: stage in smem (overlaying pool), coalesced STG.128 ----
    __syncthreads();
    float* ys = pool;

    const int kb = 16 * tip;
    #pragma unroll
    for (int r = 0; r < R; ++r) {
        float lo, hi;
        asm("mov.b64 {%0, %1}, %2;" : "=f"(lo), "=f"(hi) : "l"(acc[r]));
        int k1 = kb + r, k2 = kb + r + 8;
        ys[p * YPITCH + k1 + (k1 >> 4)] = lo;
        ys[p * YPITCH + k2 + (k2 >> 4)] = hi;
    }
    __syncthreads();

    const int j0  = 16 * tid;
    const int jg0 = 3 * K0 + j0;
    int m  = j0 % 3;
    int kl = j0 / 3;
    #pragma unroll
    for (int v = 0; v < 4; ++v) {
        float o[4];
        #pragma unroll
        for (int w = 0; w < 4; ++w) {
            int pm = (m == 0) ? 1 : ((m == 1) ? 0 : 2);
            o[w] = ys[pm * YPITCH + kl + (kl >> 4)];
            if (++m == 3) { m = 0; ++kl; }
        }
        int jg = jg0 + 4 * v;
        if (jg + 3 < nout) {
            *reinterpret_cast<float4*>(out + jg) =
                make_float4(o[0], o[1], o[2], o[3]);
        } else {
            #pragma unroll
            for (int w = 0; w < 4; ++w)
                if (jg + w < nout) out[jg + w] = o[w];
        }
    }
}

extern "C" void kernel_launch(void* const* d_in, const int* in_sizes, int n_in,
                              void* d_out, int out_size) {
    const float* x = (const float*)d_in[0];
    const float* h = (const float*)d_in[n_in - 1];
    float* out     = (float*)d_out;
    int N          = in_sizes[0];
    int ktotal     = (out_size + 2) / 3;
    int blocks     = (ktotal + KTILE - 1) / KTILE;
    resample_poly_kernel<<<blocks, NTHREADS>>>(x, h, out, N, ktotal, out_size);
}

// round 9
// speedup vs baseline: 1.2824x; 1.2824x over previous
#include <cuda_runtime.h>
#include <cuda_bf16.h>

// Polyphase resample up=3, down=2, F=1023 taps (341 per phase).
// Per phase p (out[j], j = jp + 3k): y_p[k] = sum_q (3*h[p+3q]) * x[c_p + 2k - q]
//   jp = {1,0,2}[p],  c_p = {171,170,171}[p]
//
// f32x2 FMA: 16 outputs/thread as 8 packed accumulators pairing (k+r, k+r+8).
// Pack (x[e], x[e+16]) slides by -1 per tap -> two parity rotating register
// windows, refilled by paired conflict-free LDS.64 from a pre-paired smem
// window. Filter pairs (v,v) live in __constant__ memory (LDC port, zero smem
// traffic, zero shift MOVs). Outputs staged in smem -> coalesced STG.128.

constexpr int NTAP3    = 341;
constexpr int HSTRIDE  = 342;    // padded per-phase tap stride
constexpr int KTILE    = 1024;
constexpr int NTHREADS = 192;    // 6 warps: 2 per phase
constexpr int R        = 8;
constexpr int WIN      = 2 * KTILE + 340;        // 2388 x-samples
constexpr int PXN      = WIN - 16;               // pairs (i, i+16)
constexpr int PXSK     = PXN + (PXN >> 5) + 4;   // skewed pair-array size
constexpr int YPITCH   = 1091;

typedef unsigned long long ull;

__constant__ ull c_h[3 * HSTRIDE];               // duplicated (3h,3h) pairs

__device__ __forceinline__ int ps(int i) { return i + (i >> 5); }  // pair skew

__device__ __forceinline__ ull ldpx(const float2* __restrict__ px, int i) {
    return *reinterpret_cast<const ull*>(px + ps(i));
}

__device__ __forceinline__ void fma2(ull& d, ull a, ull b) {
    asm("fma.rn.f32x2 %0, %1, %2, %0;" : "+l"(d) : "l"(a), "l"(b));
}

// Build duplicated scaled filter pairs into constant memory (via raw pointer).
__global__ void prep_h(const float* __restrict__ h, ull* __restrict__ ch) {
    int m = blockIdx.x * blockDim.x + threadIdx.x;
    if (m >= 3 * HSTRIDE) return;
    int p = m / HSTRIDE, q = m % HSTRIDE;
    float v = (q < NTAP3) ? 3.0f * h[p + 3 * q] : 0.0f;
    float2 pr = make_float2(v, v);
    ch[m] = *reinterpret_cast<ull*>(&pr);
}

__global__ void __launch_bounds__(NTHREADS, 4)
resample_poly_kernel(const float* __restrict__ x, float* __restrict__ out,
                     int N, int nout)
{
    __shared__ __align__(16) float2 px[PXSK];    // x window, then y staging

    const int tid = threadIdx.x;
    const int K0  = blockIdx.x * KTILE;
    const int ws  = 2 * K0 - 170;                // global x index of window start

    // Build pre-paired window: px[i] = (x[ws+i], x[ws+i+16]), zero-padded.
    for (int i = tid; i < PXN; i += NTHREADS) {
        int g  = ws + i;
        int g2 = g + 16;
        float lo = (g  >= 0 && g  < N) ? x[g]  : 0.0f;
        float hi = (g2 >= 0 && g2 < N) ? x[g2] : 0.0f;
        px[ps(i)] = make_float2(lo, hi);
    }
    __syncthreads();

    const int wid  = tid >> 5;
    const int lane = tid & 31;
    const int p    = wid >> 1;                    // phase 0..2 (2 warps each)
    const int tip  = ((wid & 1) << 5) | lane;     // 0..63 within phase
    const int cp   = (p == 1) ? 170 : 171;
    const int b    = cp + 170 + 32 * tip;         // local base index

    ull acc[R], PA[R], PB[R];
    #pragma unroll
    for (int r = 0; r < R; ++r) acc[r] = 0ull;
    #pragma unroll
    for (int r = 0; r < R; ++r) PA[r] = ldpx(px, b + 2 * r);       // even q
    #pragma unroll
    for (int r = 0; r < R; ++r) PB[r] = ldpx(px, b - 1 + 2 * r);   // odd q

    const ull* hc = c_h + p * HSTRIDE;            // constant-space pointer

    for (int qo = 0; qo < 336; qo += 16) {
        #pragma unroll
        for (int qp = 0; qp < 8; ++qp) {
            const int q = qo + 2 * qp;
            ull hA = hc[q];                        // LDC.64 (hoisted by ptxas)
            ull hB = hc[q + 1];
            #pragma unroll
            for (int r = 0; r < R; ++r) fma2(acc[r], PA[(r - qp) & 7], hA);
            PA[(7 - qp) & 7] = ldpx(px, b - q - 2);   // refill for tap q+2
            #pragma unroll
            for (int r = 0; r < R; ++r) fma2(acc[r], PB[(r - qp) & 7], hB);
            PB[(7 - qp) & 7] = ldpx(px, b - q - 3);   // refill for tap q+3
        }
    }
    // Tail taps 336..340 (b >= 340 so all pair indices >= 0).
    #pragma unroll
    for (int q = 336; q < 341; ++q) {
        ull hh = hc[q];
        #pragma unroll
        for (int r = 0; r < R; ++r) {
            ull pxx = ldpx(px, b - q + 2 * r);
            fma2(acc[r], pxx, hh);
        }
    }

    // ---- Epilogue: stage in smem (overlaying px), coalesced STG.128 ----
    __syncthreads();
    float* ys = reinterpret_cast<float*>(px);     // 3*YPITCH = 3281 floats, fits

    const int kb = 16 * tip;
    #pragma unroll
    for (int r = 0; r < R; ++r) {
        float lo, hi;
        asm("mov.b64 {%0, %1}, %2;" : "=f"(lo), "=f"(hi) : "l"(acc[r]));
        int k1 = kb + r, k2 = kb + r + 8;
        ys[p * YPITCH + k1 + (k1 >> 4)] = lo;
        ys[p * YPITCH + k2 + (k2 >> 4)] = hi;
    }
    __syncthreads();

    const int j0  = 16 * tid;
    const int jg0 = 3 * K0 + j0;
    int m  = j0 % 3;
    int kl = j0 / 3;
    #pragma unroll
    for (int v = 0; v < 4; ++v) {
        float o[4];
        #pragma unroll
        for (int w = 0; w < 4; ++w) {
            int pm = (m == 0) ? 1 : ((m == 1) ? 0 : 2);
            o[w] = ys[pm * YPITCH + kl + (kl >> 4)];
            if (++m == 3) { m = 0; ++kl; }
        }
        int jg = jg0 + 4 * v;
        if (jg + 3 < nout) {
            *reinterpret_cast<float4*>(out + jg) =
                make_float4(o[0], o[1], o[2], o[3]);
        } else {
            #pragma unroll
            for (int w = 0; w < 4; ++w)
                if (jg + w < nout) out[jg + w] = o[w];
        }
    }
}

extern "C" void kernel_launch(void* const* d_in, const int* in_sizes, int n_in,
                              void* d_out, int out_size) {
    const float* x = (const float*)d_in[0];
    const float* h = (const float*)d_in[n_in - 1];
    float* out     = (float*)d_out;
    int N          = in_sizes[0];
    int ktotal     = (out_size + 2) / 3;
    int blocks     = (ktotal + KTILE - 1) / KTILE;

    static ull* ch_dev = nullptr;                 // resolved once (not a stream op)
    if (!ch_dev) cudaGetSymbolAddress((void**)&ch_dev, c_h);

    prep_h<<<(3 * HSTRIDE + 255) / 256, 256>>>(h, ch_dev);
    resample_poly_kernel<<<blocks, NTHREADS>>>(x, out, N, out_size);
}

// round 12
// speedup vs baseline: 1.6099x; 1.2554x over previous
#include <cuda_runtime.h>
#include <cuda_bf16.h>

// Polyphase resample up=3, down=2, F=1023 taps (341 per phase).
// Per phase p (out[j], j = jp + 3k): y_p[k] = sum_q (3*h[p+3q]) * x[c_p + 2k - q]
//   jp = {1,0,2}[p],  c_p = {171,170,171}[p]
//
// f32x2 FMA, phases processed SEQUENTIALLY per block with literal phase
// constants so every filter load has a provably-uniform constant address
// (LDCU -> UR operand -> FFMA2 reads only 2 GPR bank pairs, rt 3 -> 2).
// Window: pre-paired (x[e],x[e+16]) smem, conflict-free LDS.64 refills into
// two parity rotating register windows. Epilogue: smem redistribute ->
// stride-3 STG (3-4 lines/warp-store).

constexpr int NTAP3    = 341;
constexpr int HSTRIDE  = 342;
constexpr int T        = 128;    // threads (4 warps)
constexpr int KPT      = 2048;   // k per phase per block (= 16*T)
constexpr int R        = 8;
constexpr int WIN      = 2 * KPT + 340;          // 4436
constexpr int PXN      = WIN - 16;               // 4420 pairs
constexpr int PXSK     = PXN + (PXN >> 5) + 4;   // 4562
constexpr int YSN      = KPT + (KPT >> 4);       // 2176 staged floats

typedef unsigned long long ull;

__constant__ ull c_h[3 * HSTRIDE];               // duplicated (3h,3h) pairs

__device__ __forceinline__ int ps(int i) { return i + (i >> 5); }

__device__ __forceinline__ ull ldpx(const float2* __restrict__ px, int i) {
    return *reinterpret_cast<const ull*>(px + ps(i));
}
__device__ __forceinline__ void fma2(ull& d, ull a, ull b) {
    asm("fma.rn.f32x2 %0, %1, %2, %0;" : "+l"(d) : "l"(a), "l"(b));
}

__global__ void prep_h(const float* __restrict__ h, ull* __restrict__ ch) {
    int m = blockIdx.x * blockDim.x + threadIdx.x;
    if (m >= 3 * HSTRIDE) return;
    int p = m / HSTRIDE, q = m % HSTRIDE;
    float v = (q < NTAP3) ? 3.0f * h[p + 3 * q] : 0.0f;
    float2 pr = make_float2(v, v);
    ch[m] = *reinterpret_cast<ull*>(&pr);
}

template <int P>
__device__ __forceinline__ void do_phase(const float2* __restrict__ px,
                                         float* __restrict__ ys,
                                         float* __restrict__ out,
                                         int K0, int nout)
{
    const int t  = threadIdx.x;
    const int cp = (P == 1) ? 170 : 171;
    const int jp = (P == 0) ? 1 : ((P == 1) ? 0 : 2);
    const int b  = cp + 170 + 32 * t;

    ull acc[R], PA[R], PB[R];
    #pragma unroll
    for (int r = 0; r < R; ++r) acc[r] = 0ull;
    #pragma unroll
    for (int r = 0; r < R; ++r) PA[r] = ldpx(px, b + 2 * r);       // even q
    #pragma unroll
    for (int r = 0; r < R; ++r) PB[r] = ldpx(px, b - 1 + 2 * r);   // odd q

    for (int qo = 0; qo < 336; qo += 16) {
        #pragma unroll
        for (int qp = 0; qp < 8; ++qp) {
            const int q = qo + 2 * qp;
            // Literal base + uniform loop counter -> LDCU (uniform const port)
            ull hA = c_h[P * HSTRIDE + q];
            ull hB = c_h[P * HSTRIDE + q + 1];
            #pragma unroll
            for (int r = 0; r < R; ++r) fma2(acc[r], PA[(r - qp) & 7], hA);
            PA[(7 - qp) & 7] = ldpx(px, b - q - 2);
            #pragma unroll
            for (int r = 0; r < R; ++r) fma2(acc[r], PB[(r - qp) & 7], hB);
            PB[(7 - qp) & 7] = ldpx(px, b - q - 3);
        }
    }
    #pragma unroll
    for (int q = 336; q < 341; ++q) {
        ull hh = c_h[P * HSTRIDE + q];
        #pragma unroll
        for (int r = 0; r < R; ++r) {
            ull pxx = ldpx(px, b - q + 2 * r);
            fma2(acc[r], pxx, hh);
        }
    }

    // Stage into ys (skewed: lane word-stride 17, conflict-free), then
    // redistribute so lanes write consecutive k (out-stride 3 = 3-4 lines).
    __syncthreads();   // previous phase's ys readers are done
    const int kb = 16 * t;
    #pragma unroll
    for (int r = 0; r < R; ++r) {
        float lo, hi;
        asm("mov.b64 {%0, %1}, %2;" : "=f"(lo), "=f"(hi) : "l"(acc[r]));
        int k1 = kb + r, k2 = kb + r + 8;
        ys[k1 + (k1 >> 4)] = lo;
        ys[k2 + (k2 >> 4)] = hi;
    }
    __syncthreads();
    #pragma unroll
    for (int u = 0; u < 16; ++u) {
        int kloc = t + T * u;
        float v = ys[kloc + (kloc >> 4)];
        int jg = jp + 3 * (K0 + kloc);
        if (jg < nout) out[jg] = v;
    }
}

__global__ void __launch_bounds__(T, 5)
resample_poly_kernel(const float* __restrict__ x, float* __restrict__ out,
                     int N, int nout)
{
    __shared__ __align__(16) float2 px[PXSK];
    __shared__ float ys[YSN];

    const int tid = threadIdx.x;
    const int K0  = blockIdx.x * KPT;
    const int ws  = 2 * K0 - 170;

    for (int i = tid; i < PXN; i += T) {
        int g  = ws + i;
        int g2 = g + 16;
        float lo = (g  >= 0 && g  < N) ? x[g]  : 0.0f;
        float hi = (g2 >= 0 && g2 < N) ? x[g2] : 0.0f;
        px[ps(i)] = make_float2(lo, hi);
    }
    __syncthreads();

    do_phase<0>(px, ys, out, K0, nout);
    do_phase<1>(px, ys, out, K0, nout);
    do_phase<2>(px, ys, out, K0, nout);
}

extern "C" void kernel_launch(void* const* d_in, const int* in_sizes, int n_in,
                              void* d_out, int out_size) {
    const float* x = (const float*)d_in[0];
    const float* h = (const float*)d_in[n_in - 1];
    float* out     = (float*)d_out;
    int N          = in_sizes[0];
    int ktotal     = (out_size + 2) / 3;
    int blocks     = (ktotal + KPT - 1) / KPT;   // 2048 for this problem

    static ull* ch_dev = nullptr;
    if (!ch_dev) cudaGetSymbolAddress((void**)&ch_dev, c_h);

    prep_h<<<(3 * HSTRIDE + 255) / 256, 256>>>(h, ch_dev);
    resample_poly_kernel<<<blocks, T>>>(x, out, N, out_size);
}

// round 14
// speedup vs baseline: 1.8720x; 1.1628x over previous
#include <cuda_runtime.h>
#include <cuda_bf16.h>

// Polyphase resample up=3, down=2, F=1023 taps (341 per phase).
// Per phase p (out[j], j = jp + 3k): y_p[k] = sum_q (3*h[p+3q]) * x[c_p + 2k - q]
//   jp = {1,0,2}[p],  c_p = {171,170,171}[p]
//
// Phases processed sequentially per block (literal phase constants -> LDCU
// uniform filter loads -> FFMA2 with UR multiplier = 2 GPR bank reads).
// Main loop in 32-tap chunks: since b mod 32 is thread-invariant and chunk
// stride == skew period, all LDS refill addresses strength-reduce to
// [pW + compile-time-imm] with one pointer decrement per chunk. Filter pair
// (hA,hB) fetched as one LDCU.128.

constexpr int NTAP3    = 341;
constexpr int HSTRIDE  = 342;
constexpr int T        = 128;    // threads (4 warps)
constexpr int KPT      = 2048;   // k per phase per block (= 16*T)
constexpr int R        = 8;
constexpr int WIN      = 2 * KPT + 340;          // 4436
constexpr int PXN      = WIN - 16;               // 4420 pairs
constexpr int PXSK     = PXN + (PXN >> 5) + 4;   // 4562
constexpr int YSN      = KPT + (KPT >> 4);       // 2176 staged floats

typedef unsigned long long ull;

__constant__ ull c_h[3 * HSTRIDE];               // duplicated (3h,3h) pairs

__device__ __forceinline__ int ps(int i) { return i + (i >> 5); }
// ps(e) for e = 32*f + (v mod 32): compile-time offset part.
__host__ __device__ constexpr int offCh(int v) {
    return 33 * (v / 32) + (v % 32);
}

__device__ __forceinline__ ull ldpx(const float2* __restrict__ px, int i) {
    return *reinterpret_cast<const ull*>(px + ps(i));
}
__device__ __forceinline__ ull ld64(const float2* __restrict__ p) {
    return *reinterpret_cast<const ull*>(p);
}
__device__ __forceinline__ void fma2(ull& d, ull a, ull b) {
    asm("fma.rn.f32x2 %0, %1, %2, %0;" : "+l"(d) : "l"(a), "l"(b));
}

__global__ void prep_h(const float* __restrict__ h, ull* __restrict__ ch) {
    int m = blockIdx.x * blockDim.x + threadIdx.x;
    if (m >= 3 * HSTRIDE) return;
    int p = m / HSTRIDE, q = m % HSTRIDE;
    float v = (q < NTAP3) ? 3.0f * h[p + 3 * q] : 0.0f;
    float2 pr = make_float2(v, v);
    ch[m] = *reinterpret_cast<ull*>(&pr);
}

template <int P>
__device__ __forceinline__ void do_phase(const float2* __restrict__ px,
                                         float* __restrict__ ys,
                                         float* __restrict__ out,
                                         int K0, int nout)
{
    constexpr int cp = (P == 1) ? 170 : 171;
    constexpr int jp = (P == 0) ? 1 : ((P == 1) ? 0 : 2);
    const int t = threadIdx.x;
    const int b = cp + 170 + 32 * t;

    ull acc[R], PA[R], PB[R];
    #pragma unroll
    for (int r = 0; r < R; ++r) acc[r] = 0ull;
    #pragma unroll
    for (int r = 0; r < R; ++r) PA[r] = ldpx(px, b + 2 * r);       // even q
    #pragma unroll
    for (int r = 0; r < R; ++r) PB[r] = ldpx(px, b - 1 + 2 * r);   // odd q

    const float2* pW = px + 33 * t;                 // chunk base pointer
    const ull*    hp = c_h + P * HSTRIDE;           // uniform filter pointer

    // 10 chunks x 32 taps (taps 0..319).
    for (int c = 0; c < 10; ++c) {
        #pragma unroll
        for (int qp = 0; qp < 16; ++qp) {
            ulonglong2 hv = *reinterpret_cast<const ulonglong2*>(hp + 2 * qp);
            #pragma unroll
            for (int r = 0; r < R; ++r) fma2(acc[r], PA[(r - qp) & 7], hv.x);
            PA[(7 - qp) & 7] = ld64(pW + offCh(cp + 168 - 2 * qp));
            #pragma unroll
            for (int r = 0; r < R; ++r) fma2(acc[r], PB[(r - qp) & 7], hv.y);
            PB[(7 - qp) & 7] = ld64(pW + offCh(cp + 167 - 2 * qp));
        }
        pW -= 33;
        hp += 32;
    }
    // Half chunk: taps 320..335 (rotation phase preserved: 160 % 8 == 0).
    #pragma unroll
    for (int qp = 0; qp < 8; ++qp) {
        ulonglong2 hv = *reinterpret_cast<const ulonglong2*>(hp + 2 * qp);
        #pragma unroll
        for (int r = 0; r < R; ++r) fma2(acc[r], PA[(r - qp) & 7], hv.x);
        PA[(7 - qp) & 7] = ld64(pW + offCh(cp + 168 - 2 * qp));
        #pragma unroll
        for (int r = 0; r < R; ++r) fma2(acc[r], PB[(r - qp) & 7], hv.y);
        PB[(7 - qp) & 7] = ld64(pW + offCh(cp + 167 - 2 * qp));
    }
    // Tail taps 336..340 (fresh loads; e = b-340+2r >= 0).
    #pragma unroll
    for (int q = 336; q < 341; ++q) {
        ull hh = hp[q - 320];
        #pragma unroll
        for (int r = 0; r < R; ++r) {
            ull pxx = ldpx(px, b - q + 2 * r);
            fma2(acc[r], pxx, hh);
        }
    }

    // Stage (skewed, conflict-free), redistribute, stride-3 STG.
    __syncthreads();
    const int kb = 16 * t;
    #pragma unroll
    for (int r = 0; r < R; ++r) {
        float lo, hi;
        asm("mov.b64 {%0, %1}, %2;" : "=f"(lo), "=f"(hi) : "l"(acc[r]));
        int k1 = kb + r, k2 = kb + r + 8;
        ys[k1 + (k1 >> 4)] = lo;
        ys[k2 + (k2 >> 4)] = hi;
    }
    __syncthreads();
    #pragma unroll
    for (int u = 0; u < 16; ++u) {
        int kloc = t + T * u;
        float v = ys[kloc + (kloc >> 4)];
        int jg = jp + 3 * (K0 + kloc);
        if (jg < nout) out[jg] = v;
    }
}

__global__ void __launch_bounds__(T, 5)
resample_poly_kernel(const float* __restrict__ x, float* __restrict__ out,
                     int N, int nout)
{
    __shared__ __align__(16) float2 px[PXSK];
    __shared__ float ys[YSN];

    const int tid = threadIdx.x;
    const int K0  = blockIdx.x * KPT;
    const int ws  = 2 * K0 - 170;

    for (int i = tid; i < PXN; i += T) {
        int g  = ws + i;
        int g2 = g + 16;
        float lo = (g  >= 0 && g  < N) ? x[g]  : 0.0f;
        float hi = (g2 >= 0 && g2 < N) ? x[g2] : 0.0f;
        px[ps(i)] = make_float2(lo, hi);
    }
    __syncthreads();

    do_phase<0>(px, ys, out, K0, nout);
    do_phase<1>(px, ys, out, K0, nout);
    do_phase<2>(px, ys, out, K0, nout);
}

extern "C" void kernel_launch(void* const* d_in, const int* in_sizes, int n_in,
                              void* d_out, int out_size) {
    const float* x = (const float*)d_in[0];
    const float* h = (const float*)d_in[n_in - 1];
    float* out     = (float*)d_out;
    int N          = in_sizes[0];
    int ktotal     = (out_size + 2) / 3;
    int blocks     = (ktotal + KPT - 1) / KPT;   // 2048

    static ull* ch_dev = nullptr;
    if (!ch_dev) cudaGetSymbolAddress((void**)&ch_dev, c_h);

    prep_h<<<(3 * HSTRIDE + 255) / 256, 256>>>(h, ch_dev);
    resample_poly_kernel<<<blocks, T>>>(x, out, N, out_size);
}